// round 16
// baseline (speedup 1.0000x reference)
#include <cuda_runtime.h>
#include <cuda_bf16.h>
#include <math.h>
#include <stdint.h>

#define BATCH   8
#define CHN     512
#define NPOS    9216         // 96*96
#define IMGW    96
#define HEADS   4
#define HD      128
#define QUARTER 2304         // NPOS/4
#define KV_SPLIT 18
#define KV_CHUNK 512         // NPOS / KV_SPLIT
#define LN1E4_256 0.0359779077f   // ln(10000)/256

// ---------------- scratch (device globals; no allocation allowed) -------------
__device__ float g_q[BATCH * CHN * NPOS];                       // raw q
__device__ float g_k[BATCH * CHN * NPOS];                       // raw k
__device__ float g_Sp[BATCH * CHN * 72];                        // per-CTA column sums of k
__device__ float g_kmean[BATCH * HEADS * HD];
__device__ float g_z[BATCH * HEADS * NPOS];
__device__ float g_kvp[BATCH * HEADS * KV_SPLIT * HD * HD];
__device__ float g_kv[BATCH * HEADS * HD * HD];
__device__ uint4 g_wh4[1024 * 64];                              // W bf16 hi (8 bf16/uint4)
__device__ uint4 g_wl4[1024 * 64];                              // W bf16 lo

__device__ __forceinline__ float elu1(float v) {
    return v > 0.f ? v + 1.f : expf(v);
}

// ---------------- warp MMA helpers (classic mma.sync, verified R12-R14) -------
__device__ __forceinline__ uint32_t smem_u32(const void* p) {
    uint32_t a;
    asm("{ .reg .u64 t; cvta.to.shared.u64 t, %1; cvt.u32.u64 %0, t; }" : "=r"(a) : "l"(p));
    return a;
}
__device__ __forceinline__ void ldsm_x4(uint32_t* r, uint32_t addr) {
    asm volatile("ldmatrix.sync.aligned.m8n8.x4.shared.b16 {%0,%1,%2,%3}, [%4];"
        : "=r"(r[0]), "=r"(r[1]), "=r"(r[2]), "=r"(r[3]) : "r"(addr));
}
__device__ __forceinline__ void ldsm_x2(uint32_t* r, uint32_t addr) {
    asm volatile("ldmatrix.sync.aligned.m8n8.x2.shared.b16 {%0,%1}, [%2];"
        : "=r"(r[0]), "=r"(r[1]) : "r"(addr));
}
__device__ __forceinline__ void mma_bf16(float* d, const uint32_t* a, const uint32_t* b) {
    asm volatile(
        "mma.sync.aligned.m16n8k16.row.col.f32.bf16.bf16.f32 "
        "{%0,%1,%2,%3}, {%4,%5,%6,%7}, {%8,%9}, {%0,%1,%2,%3};"
        : "+f"(d[0]), "+f"(d[1]), "+f"(d[2]), "+f"(d[3])
        : "r"(a[0]), "r"(a[1]), "r"(a[2]), "r"(a[3]), "r"(b[0]), "r"(b[1]));
}
__device__ __forceinline__ uint32_t bfpack2(float a, float b) {
    __nv_bfloat16 ha = __float2bfloat16(a), hb = __float2bfloat16(b);
    uint16_t ua = *(uint16_t*)&ha, ub = *(uint16_t*)&hb;
    return (uint32_t)ua | ((uint32_t)ub << 16);
}
__device__ __forceinline__ float bfres(float v) {
    return v - __bfloat162float(__float2bfloat16(v));
}

#define QK_STRIDE 40   // bf16 elems per smem row (80 B)

// ============================================================================
// Kernel 0: one-time W_qk -> bf16 hi/lo split (packed 8 bf16 per uint4)
// ============================================================================
__global__ void wsplit_kernel(const float* __restrict__ Wqk) {
    int idx = blockIdx.x * 256 + threadIdx.x;      // 65536 items of 8 elems
    if (idx >= 1024 * 64) return;
    const float* src = &Wqk[(size_t)idx * 8];
    float v[8];
#pragma unroll
    for (int i = 0; i < 8; i++) v[i] = src[i];
    uint4 h, l;
    h.x = bfpack2(v[0], v[1]); h.y = bfpack2(v[2], v[3]);
    h.z = bfpack2(v[4], v[5]); h.w = bfpack2(v[6], v[7]);
    l.x = bfpack2(bfres(v[0]), bfres(v[1])); l.y = bfpack2(bfres(v[2]), bfres(v[3]));
    l.z = bfpack2(bfres(v[4]), bfres(v[5])); l.w = bfpack2(bfres(v[6]), bfres(v[7]));
    g_wh4[idx] = h;
    g_wl4[idx] = l;
}

// ============================================================================
// Kernel 1 (HMMA): qk[b] = W_qk @ X[b], bf16-split, bias+elu+1,
// fused per-CTA k column sums -> g_Sp.
// GRID SWAP (R16): blockIdx.x = bM (8, fastest), blockIdx.y = bN (72) so the
// 8 CTAs sharing one X n-slice co-run and hit L2 instead of re-pulling DRAM.
// ============================================================================
__global__ __launch_bounds__(256, 2)
void qk_mma_kernel(const float* __restrict__ x,
                   const float* __restrict__ bqk) {
    __shared__ __align__(16) __nv_bfloat16 Ah[128][QK_STRIDE];
    __shared__ __align__(16) __nv_bfloat16 Al[128][QK_STRIDE];
    __shared__ __align__(16) __nv_bfloat16 Bh[128][QK_STRIDE];
    __shared__ __align__(16) __nv_bfloat16 Bl[128][QK_STRIDE];
    __shared__ float redS[128][4];

    const int bM = blockIdx.x * 128;      // out-channel block (fastest)
    const int bN = blockIdx.y * 128;      // n block
    const int bb = blockIdx.z;
    const float* X = x + (size_t)bb * CHN * NPOS;

    const int tid = threadIdx.x;
    const int wid = tid >> 5, lane = tid & 31;
    const int wm = wid & 1;
    const int wn = wid >> 1;

    float acc[4][4][4];
#pragma unroll
    for (int i = 0; i < 4; i++)
#pragma unroll
        for (int j = 0; j < 4; j++)
#pragma unroll
            for (int r = 0; r < 4; r++) acc[i][j][r] = 0.f;

    const int nb = tid & 127;
    const int kg = tid >> 7;

    for (int c = 0; c < 16; c++) {
        const int k0 = c * 32;
        // A tile: precomputed bf16 hi/lo — pure copy (2 items/thread)
#pragma unroll
        for (int r = 0; r < 2; r++) {
            int f = tid + r * 256;          // 512 items
            int row = f >> 2, qg = f & 3;   // 8-elem groups
            int gi = (bM + row) * 64 + c * 4 + qg;
            uint4 h = g_wh4[gi];
            uint4 l = g_wl4[gi];
            *(uint2*)&Ah[row][qg * 8]     = make_uint2(h.x, h.y);
            *(uint2*)&Ah[row][qg * 8 + 4] = make_uint2(h.z, h.w);
            *(uint2*)&Al[row][qg * 8]     = make_uint2(l.x, l.y);
            *(uint2*)&Al[row][qg * 8 + 4] = make_uint2(l.z, l.w);
        }
        // B tile: X[k][bN+n] -> [n][k] bf16 hi/lo
#pragma unroll
        for (int r = 0; r < 4; r++) {
            int kk = kg * 16 + r * 4;
            const float* px = &X[(size_t)(k0 + kk) * NPOS + bN + nb];
            float v0 = px[0], v1 = px[NPOS], v2 = px[2 * NPOS], v3 = px[3 * NPOS];
            *(uint2*)&Bh[nb][kk] = make_uint2(bfpack2(v0, v1), bfpack2(v2, v3));
            *(uint2*)&Bl[nb][kk] = make_uint2(bfpack2(bfres(v0), bfres(v1)),
                                              bfpack2(bfres(v2), bfres(v3)));
        }
        __syncthreads();

#pragma unroll
        for (int ks = 0; ks < 2; ks++) {
            uint32_t bh[4][2], bl[4][2];
#pragma unroll
            for (int nf = 0; nf < 4; nf++) {
                int nrow = wn * 32 + nf * 8 + (lane & 7);
                int kcol = ks * 16 + ((lane >> 3) & 1) * 8;
                ldsm_x2(bh[nf], smem_u32(&Bh[nrow][kcol]));
                ldsm_x2(bl[nf], smem_u32(&Bl[nrow][kcol]));
            }
#pragma unroll
            for (int mf = 0; mf < 4; mf++) {
                int mrow = wm * 64 + mf * 16 + (lane & 15);
                int kcol = ks * 16 + (lane >> 4) * 8;
                uint32_t ah[4], al[4];
                ldsm_x4(ah, smem_u32(&Ah[mrow][kcol]));
                ldsm_x4(al, smem_u32(&Al[mrow][kcol]));
#pragma unroll
                for (int nf = 0; nf < 4; nf++) {
                    mma_bf16(acc[mf][nf], ah, bh[nf]);
                    mma_bf16(acc[mf][nf], ah, bl[nf]);
                    mma_bf16(acc[mf][nf], al, bh[nf]);
                }
            }
        }
        __syncthreads();
    }

    const bool is_k = (blockIdx.x >= 4);
#pragma unroll
    for (int mf = 0; mf < 4; mf++) {
#pragma unroll
        for (int h = 0; h < 2; h++) {
            int rowg = bM + wm * 64 + mf * 16 + (lane >> 2) + h * 8;
            float bias = bqk[rowg];
            float* dst = (rowg < CHN)
                ? &g_q[((size_t)bb * CHN + rowg) * NPOS]
                : &g_k[((size_t)bb * CHN + (rowg - CHN)) * NPOS];
            float rs = 0.f;
#pragma unroll
            for (int nf = 0; nf < 4; nf++) {
                int colg = bN + wn * 32 + nf * 8 + (lane & 3) * 2;
                float2 o;
                o.x = elu1(acc[mf][nf][h * 2 + 0] + bias);
                o.y = elu1(acc[mf][nf][h * 2 + 1] + bias);
                *(float2*)&dst[colg] = o;
                rs += o.x + o.y;
            }
            if (is_k) {          // block-uniform condition; shfl safe
                rs += __shfl_xor_sync(0xffffffffu, rs, 1);
                rs += __shfl_xor_sync(0xffffffffu, rs, 2);
                if ((lane & 3) == 0)
                    redS[wm * 64 + mf * 16 + (lane >> 2) + h * 8][wn] = rs;
            }
        }
    }
    if (is_k) {
        __syncthreads();
        if (tid < 128) {
            float tot = redS[tid][0] + redS[tid][1] + redS[tid][2] + redS[tid][3];
            int kRow = bM - CHN + tid;
            g_Sp[((size_t)bb * CHN + kRow) * 72 + (bN >> 7)] = tot;
        }
    }
}

// ============================================================================
// Kernel 2: k_mean from g_Sp (72 block sums per channel; quarter hh = 18 blocks)
// ============================================================================
__global__ void kmean_kernel() {
    int idx = blockIdx.x * 256 + threadIdx.x;   // 4096
    if (idx >= BATCH * HEADS * HD) return;
    int d  = idx & 127;
    int hh = (idx >> 7) & 3;
    int bb = idx >> 9;
    float s = 0.f;
#pragma unroll
    for (int j = 0; j < 4; j++) {
        const float* p = &g_Sp[((size_t)bb * CHN + 128 * j + d) * 72 + hh * 18];
#pragma unroll
        for (int t = 0; t < 18; t++) s += p[t];
    }
    g_kmean[idx] = s * (1.f / NPOS);
}

// ============================================================================
// Kernel 3: z = 1 / (q_raw . k_mean + eps)
// ============================================================================
__global__ __launch_bounds__(256) void z_kernel() {
    const int chunk = blockIdx.x;
    const int hh = blockIdx.y, bb = blockIdx.z;
    const int tid = threadIdx.x;
    __shared__ float km[HD];
    if (tid < HD) km[tid] = g_kmean[((size_t)bb * HEADS + hh) * HD + tid];
    __syncthreads();
    const int rp = chunk * 256 + tid;
    const float* qbase = g_q + (size_t)bb * CHN * NPOS + (size_t)hh * QUARTER + rp;
    float a0 = 0.f, a1 = 0.f, a2 = 0.f, a3 = 0.f;
#pragma unroll 4
    for (int d = 0; d < HD; d++) {
        float kmv = km[d];
        a0 += qbase[(size_t)(d)       * NPOS] * kmv;
        a1 += qbase[(size_t)(128 + d) * NPOS] * kmv;
        a2 += qbase[(size_t)(256 + d) * NPOS] * kmv;
        a3 += qbase[(size_t)(384 + d) * NPOS] * kmv;
    }
    float* zb = &g_z[((size_t)bb * HEADS + hh) * NPOS + 4 * rp];
    zb[0] = 1.f / (a0 + 1e-6f);
    zb[1] = 1.f / (a1 + 1e-6f);
    zb[2] = 1.f / (a2 + 1e-6f);
    zb[3] = 1.f / (a3 + 1e-6f);
}

// ============================================================================
// Kernel 4 (HMMA + fused RoPE): kv partials (R13-verified body)
// ============================================================================
__global__ __launch_bounds__(256, 2)
void kv_hmma_kernel(const float* __restrict__ x) {
    __shared__ __align__(16) __nv_bfloat16 Ah[128][QK_STRIDE];
    __shared__ __align__(16) __nv_bfloat16 Al[128][QK_STRIDE];
    __shared__ __align__(16) __nv_bfloat16 Bh[128][QK_STRIDE];
    __shared__ __align__(16) __nv_bfloat16 Bl[128][QK_STRIDE];

    const int chunk = blockIdx.x;
    const int hh = blockIdx.y, bb = blockIdx.z;
    const int tid = threadIdx.x;
    const int wid = tid >> 5, lane = tid & 31;
    const int wm = wid & 1, wn = wid >> 1;

    float acc[4][4][4];
#pragma unroll
    for (int i = 0; i < 4; i++)
#pragma unroll
        for (int j = 0; j < 4; j++)
#pragma unroll
            for (int r = 0; r < 4; r++) acc[i][j][r] = 0.f;

    const float* kr = &g_k[((size_t)bb * CHN + 128 * hh) * NPOS];

    float th[2], ctb[2], stb[2];
#pragma unroll
    for (int r = 0; r < 2; r++) {
        int pd = (tid + r * 256) >> 3;
        float p = (float)(64 * hh + pd);
        th[r] = expf(p * -LN1E4_256);
        sincosf(th[r], &stb[r], &ctb[r]);
    }

    for (int t = 0; t < 16; t++) {
        const int m0 = chunk * KV_CHUNK + t * 32;
#pragma unroll
        for (int r = 0; r < 2; r++) {
            int item = tid + r * 256;
            int pd = item >> 3, g = item & 7;
            const float* pre = &kr[(size_t)(2 * pd) * NPOS + m0 + 4 * g];
            float4 re4 = *(const float4*)pre;
            float4 im4 = *(const float4*)(pre + NPOS);
            float rev[4] = {re4.x, re4.y, re4.z, re4.w};
            float imv[4] = {im4.x, im4.y, im4.z, im4.w};
            int col0 = (m0 + 4 * g) % IMGW;
            float s, c;
            sincosf((float)col0 * th[r], &s, &c);
            float ore[4], oim[4];
#pragma unroll
            for (int i = 0; i < 4; i++) {
                ore[i] = c * rev[i] - s * imv[i];
                oim[i] = s * rev[i] + c * imv[i];
                float cn = c * ctb[r] - s * stb[r];
                s = s * ctb[r] + c * stb[r];
                c = cn;
            }
            *(uint2*)&Ah[2 * pd][4 * g]     = make_uint2(bfpack2(ore[0], ore[1]), bfpack2(ore[2], ore[3]));
            *(uint2*)&Ah[2 * pd + 1][4 * g] = make_uint2(bfpack2(oim[0], oim[1]), bfpack2(oim[2], oim[3]));
            *(uint2*)&Al[2 * pd][4 * g]     = make_uint2(bfpack2(bfres(ore[0]), bfres(ore[1])),
                                                          bfpack2(bfres(ore[2]), bfres(ore[3])));
            *(uint2*)&Al[2 * pd + 1][4 * g] = make_uint2(bfpack2(bfres(oim[0]), bfres(oim[1])),
                                                          bfpack2(bfres(oim[2]), bfres(oim[3])));
        }
        {
            const int posb = hh * QUARTER + (m0 >> 2);
            int rg = tid & 1, j = (tid >> 1) & 3, ebase = tid >> 3;
#pragma unroll
            for (int r = 0; r < 4; r++) {
                int e = ebase + 32 * r;
                float4 v = *(const float4*)(x + ((size_t)bb * CHN + 128 * j + e) * NPOS + posb + rg * 4);
                float vv[4] = {v.x, v.y, v.z, v.w};
#pragma unroll
                for (int u = 0; u < 4; u++) {
                    int ml = 4 * (rg * 4 + u) + j;
                    __nv_bfloat16 h = __float2bfloat16(vv[u]);
                    Bh[e][ml] = h;
                    Bl[e][ml] = __float2bfloat16(vv[u] - __bfloat162float(h));
                }
            }
        }
        __syncthreads();

#pragma unroll
        for (int ks = 0; ks < 2; ks++) {
            uint32_t bh[4][2], bl[4][2];
#pragma unroll
            for (int nf = 0; nf < 4; nf++) {
                int nrow = wn * 32 + nf * 8 + (lane & 7);
                int kcol = ks * 16 + ((lane >> 3) & 1) * 8;
                ldsm_x2(bh[nf], smem_u32(&Bh[nrow][kcol]));
                ldsm_x2(bl[nf], smem_u32(&Bl[nrow][kcol]));
            }
#pragma unroll
            for (int mf = 0; mf < 4; mf++) {
                int mrow = wm * 64 + mf * 16 + (lane & 15);
                int kcol = ks * 16 + (lane >> 4) * 8;
                uint32_t ah[4], al[4];
                ldsm_x4(ah, smem_u32(&Ah[mrow][kcol]));
                ldsm_x4(al, smem_u32(&Al[mrow][kcol]));
#pragma unroll
                for (int nf = 0; nf < 4; nf++) {
                    mma_bf16(acc[mf][nf], ah, bh[nf]);
                    mma_bf16(acc[mf][nf], ah, bl[nf]);
                    mma_bf16(acc[mf][nf], al, bh[nf]);
                }
            }
        }
        __syncthreads();
    }

    float* dst = &g_kvp[(((size_t)(bb * HEADS + hh)) * KV_SPLIT + chunk) * HD * HD];
#pragma unroll
    for (int mf = 0; mf < 4; mf++) {
#pragma unroll
        for (int h = 0; h < 2; h++) {
            int d = wm * 64 + mf * 16 + (lane >> 2) + h * 8;
#pragma unroll
            for (int nf = 0; nf < 4; nf++) {
                int e = wn * 32 + nf * 8 + (lane & 3) * 2;
                *(float2*)&dst[d * HD + e] =
                    make_float2(acc[mf][nf][h * 2 + 0], acc[mf][nf][h * 2 + 1]);
            }
        }
    }
}

__global__ void kvreduce_kernel() {
    int idx = blockIdx.x * 256 + threadIdx.x;
    int bh  = idx >> 14;
    int off = idx & 16383;
    const float* p = &g_kvp[((size_t)bh * KV_SPLIT) * HD * HD + off];
    float s = 0.f;
#pragma unroll
    for (int c = 0; c < KV_SPLIT; c++) s += p[(size_t)c * HD * HD];
    g_kv[idx] = s * (1.f / NPOS);
}

// ============================================================================
// Kernel 6 (HMMA + fused RoPE): out (R13-verified body)
// ============================================================================
__global__ __launch_bounds__(256, 2)
void out_hmma_kernel(float* __restrict__ out) {
    __shared__ __align__(16) __nv_bfloat16 Ah[128][QK_STRIDE];
    __shared__ __align__(16) __nv_bfloat16 Al[128][QK_STRIDE];
    __shared__ __align__(16) __nv_bfloat16 Bh[128][QK_STRIDE];
    __shared__ __align__(16) __nv_bfloat16 Bl[128][QK_STRIDE];

    const int m0 = blockIdx.x * 128;
    const int hh = blockIdx.y, bb = blockIdx.z;
    const int tid = threadIdx.x;
    const int wid = tid >> 5, lane = tid & 31;
    const int wm = wid & 1, wn = wid >> 1;

    float acc[4][4][4];
#pragma unroll
    for (int i = 0; i < 4; i++)
#pragma unroll
        for (int j = 0; j < 4; j++)
#pragma unroll
            for (int r = 0; r < 4; r++) acc[i][j][r] = 0.f;

    const float* qr  = &g_q[((size_t)bb * CHN + 128 * hh) * NPOS];
    const float* kvm = &g_kv[((size_t)(bb * HEADS) + hh) * HD * HD];

    for (int dc = 0; dc < 4; dc++) {
        const int d0 = dc * 32;
#pragma unroll
        for (int r = 0; r < 4; r++) {
            int item = tid + r * 256;
            int dk = item >> 5, eg = item & 31;
            float4 v = *(const float4*)&kvm[(d0 + dk) * HD + 4 * eg];
            float vv[4] = {v.x, v.y, v.z, v.w};
#pragma unroll
            for (int i = 0; i < 4; i++) {
                int e = 4 * eg + i;
                __nv_bfloat16 h = __float2bfloat16(vv[i]);
                Ah[e][dk] = h;
                Al[e][dk] = __float2bfloat16(vv[i] - __bfloat162float(h));
            }
        }
#pragma unroll
        for (int r = 0; r < 2; r++) {
            int item = tid + r * 256;
            int u = item >> 5, g = item & 31;
            const float* pre = &qr[(size_t)(d0 + 2 * u) * NPOS + m0 + 4 * g];
            float4 re4 = *(const float4*)pre;
            float4 im4 = *(const float4*)(pre + NPOS);
            float rev[4] = {re4.x, re4.y, re4.z, re4.w};
            float imv[4] = {im4.x, im4.y, im4.z, im4.w};
            float p = (float)(64 * hh + (d0 >> 1) + u);
            float theta = expf(p * -LN1E4_256);
            float ct, st;
            sincosf(theta, &st, &ct);
            int col0 = (m0 + 4 * g) % IMGW;
            float s, c;
            sincosf((float)col0 * theta, &s, &c);
#pragma unroll
            for (int i = 0; i < 4; i++) {
                float ore = c * rev[i] - s * imv[i];
                float oim = s * rev[i] + c * imv[i];
                int m = 4 * g + i;
                __nv_bfloat16 hr = __float2bfloat16(ore);
                __nv_bfloat16 hi = __float2bfloat16(oim);
                Bh[m][2 * u]     = hr;
                Bh[m][2 * u + 1] = hi;
                Bl[m][2 * u]     = __float2bfloat16(ore - __bfloat162float(hr));
                Bl[m][2 * u + 1] = __float2bfloat16(oim - __bfloat162float(hi));
                float cn = c * ct - s * st;
                s = s * ct + c * st;
                c = cn;
            }
        }
        __syncthreads();

#pragma unroll
        for (int ks = 0; ks < 2; ks++) {
            uint32_t bh[4][2], bl[4][2];
#pragma unroll
            for (int nf = 0; nf < 4; nf++) {
                int nrow = wn * 32 + nf * 8 + (lane & 7);
                int kcol = ks * 16 + ((lane >> 3) & 1) * 8;
                ldsm_x2(bh[nf], smem_u32(&Bh[nrow][kcol]));
                ldsm_x2(bl[nf], smem_u32(&Bl[nrow][kcol]));
            }
#pragma unroll
            for (int mf = 0; mf < 4; mf++) {
                int mrow = wm * 64 + mf * 16 + (lane & 15);
                int kcol = ks * 16 + (lane >> 4) * 8;
                uint32_t ah[4], al[4];
                ldsm_x4(ah, smem_u32(&Ah[mrow][kcol]));
                ldsm_x4(al, smem_u32(&Al[mrow][kcol]));
#pragma unroll
                for (int nf = 0; nf < 4; nf++) {
                    mma_bf16(acc[mf][nf], ah, bh[nf]);
                    mma_bf16(acc[mf][nf], ah, bl[nf]);
                    mma_bf16(acc[mf][nf], al, bh[nf]);
                }
            }
        }
        __syncthreads();
    }

    const float* zb = &g_z[((size_t)bb * HEADS + hh) * NPOS + m0];
#pragma unroll
    for (int mf = 0; mf < 4; mf++) {
#pragma unroll
        for (int h = 0; h < 2; h++) {
            int e = wm * 64 + mf * 16 + (lane >> 2) + h * 8;
            float* dst = out + ((size_t)bb * CHN + 128 * hh + e) * NPOS + m0;
#pragma unroll
            for (int nf = 0; nf < 4; nf++) {
                int ml = wn * 32 + nf * 8 + (lane & 3) * 2;
                float2 o;
                o.x = acc[mf][nf][h * 2 + 0] * zb[ml + 0];
                o.y = acc[mf][nf][h * 2 + 1] * zb[ml + 1];
                *(float2*)&dst[ml] = o;
            }
        }
    }
}

// ============================================================================
// Kernel 7: lepe — depthwise 3x3 conv, out += conv + bias
// ============================================================================
__global__ __launch_bounds__(256) void lepe_kernel(const float* __restrict__ x,
                                                   const float* __restrict__ w,
                                                   const float* __restrict__ bias,
                                                   float* __restrict__ out) {
    const int c = blockIdx.x, bb = blockIdx.y;
    __shared__ float plane[NPOS];
    const float* src = x + ((size_t)bb * CHN + c) * NPOS;
    const int tid = threadIdx.x;
    for (int i = tid; i < NPOS; i += 256) plane[i] = src[i];
    float wv[9];
#pragma unroll
    for (int kk = 0; kk < 9; kk++) wv[kk] = w[c * 9 + kk];
    const float bv = bias[c];
    __syncthreads();

    float* dst = out + ((size_t)bb * CHN + c) * NPOS;
    for (int i = tid; i < NPOS; i += 256) {
        int y = i / IMGW;
        int xx = i - y * IMGW;
        float s = bv;
#pragma unroll
        for (int ky = 0; ky < 3; ky++) {
            int yy = y + ky - 1;
            if (yy < 0 || yy >= IMGW) continue;
#pragma unroll
            for (int kx = 0; kx < 3; kx++) {
                int xs = xx + kx - 1;
                if (xs < 0 || xs >= IMGW) continue;
                s += wv[ky * 3 + kx] * plane[yy * IMGW + xs];
            }
        }
        dst[i] += s;
    }
}

// ============================================================================
extern "C" void kernel_launch(void* const* d_in, const int* in_sizes, int n_in,
                              void* d_out, int out_size) {
    (void)in_sizes; (void)n_in; (void)out_size;
    const float* x    = (const float*)d_in[0];
    const float* Wqk  = (const float*)d_in[1];
    const float* bqk  = (const float*)d_in[2];
    const float* lw   = (const float*)d_in[3];
    const float* lb   = (const float*)d_in[4];
    float* out = (float*)d_out;

    // 0) one-time W split (2 MB; negligible)
    wsplit_kernel<<<256, 256>>>(Wqk);
    // 1) q,k = elu(W_qk @ x + b) + 1  + fused k column sums
    //    grid: bM fastest -> 8 CTAs sharing an X n-slice co-run (L2 reuse)
    qk_mma_kernel<<<dim3(8, 72, BATCH), 256>>>(x, bqk);
    // 2) k_mean from g_Sp
    kmean_kernel<<<16, 256>>>();
    // 3) z (raw q)
    z_kernel<<<dim3(9, HEADS, BATCH), 256>>>();
    // 4) kv = rope(k) @ v  (split-K + reduce)
    kv_hmma_kernel<<<dim3(KV_SPLIT, HEADS, BATCH), 256>>>(x);
    kvreduce_kernel<<<2048, 256>>>();
    // 5) out = z * (rope(q) @ kv)
    out_hmma_kernel<<<dim3(72, HEADS, BATCH), 256>>>(out);
    // 6) out += depthwise3x3(x) + bias
    lepe_kernel<<<dim3(CHN, BATCH), 256>>>(x, lw, lb, out);
}

// round 17
// speedup vs baseline: 1.3114x; 1.3114x over previous
#include <cuda_runtime.h>
#include <cuda_bf16.h>
#include <cuda_fp16.h>
#include <math.h>
#include <stdint.h>

#define BATCH   8
#define CHN     512
#define NPOS    9216         // 96*96
#define IMGW    96
#define HEADS   4
#define HD      128
#define QUARTER 2304         // NPOS/4
#define KV_SPLIT 18
#define KV_CHUNK 512         // NPOS / KV_SPLIT
#define LN1E4_256 0.0359779077f   // ln(10000)/256

// ---------------- scratch (device globals; no allocation allowed) -------------
__device__ float g_q[BATCH * CHN * NPOS];                       // raw q
__device__ float g_k[BATCH * CHN * NPOS];                       // raw k
__device__ float g_Sp[BATCH * CHN * 72];                        // per-CTA column sums of k
__device__ float g_kmean[BATCH * HEADS * HD];
__device__ float g_z[BATCH * HEADS * NPOS];
__device__ float g_kvp[BATCH * HEADS * KV_SPLIT * HD * HD];
__device__ float g_kv[BATCH * HEADS * HD * HD];
__device__ uint4 g_wh4[1024 * 64];                              // W fp16 (8 halfs/uint4)

__device__ __forceinline__ float elu1(float v) {
    return v > 0.f ? v + 1.f : expf(v);
}

// ---------------- warp MMA helpers (classic mma.sync, verified R12-R14) -------
__device__ __forceinline__ uint32_t smem_u32(const void* p) {
    uint32_t a;
    asm("{ .reg .u64 t; cvta.to.shared.u64 t, %1; cvt.u32.u64 %0, t; }" : "=r"(a) : "l"(p));
    return a;
}
__device__ __forceinline__ void ldsm_x4(uint32_t* r, uint32_t addr) {
    asm volatile("ldmatrix.sync.aligned.m8n8.x4.shared.b16 {%0,%1,%2,%3}, [%4];"
        : "=r"(r[0]), "=r"(r[1]), "=r"(r[2]), "=r"(r[3]) : "r"(addr));
}
__device__ __forceinline__ void ldsm_x2(uint32_t* r, uint32_t addr) {
    asm volatile("ldmatrix.sync.aligned.m8n8.x2.shared.b16 {%0,%1}, [%2];"
        : "=r"(r[0]), "=r"(r[1]) : "r"(addr));
}
__device__ __forceinline__ void mma_bf16(float* d, const uint32_t* a, const uint32_t* b) {
    asm volatile(
        "mma.sync.aligned.m16n8k16.row.col.f32.bf16.bf16.f32 "
        "{%0,%1,%2,%3}, {%4,%5,%6,%7}, {%8,%9}, {%0,%1,%2,%3};"
        : "+f"(d[0]), "+f"(d[1]), "+f"(d[2]), "+f"(d[3])
        : "r"(a[0]), "r"(a[1]), "r"(a[2]), "r"(a[3]), "r"(b[0]), "r"(b[1]));
}
__device__ __forceinline__ void mma_f16(float* d, const uint32_t* a, const uint32_t* b) {
    asm volatile(
        "mma.sync.aligned.m16n8k16.row.col.f32.f16.f16.f32 "
        "{%0,%1,%2,%3}, {%4,%5,%6,%7}, {%8,%9}, {%0,%1,%2,%3};"
        : "+f"(d[0]), "+f"(d[1]), "+f"(d[2]), "+f"(d[3])
        : "r"(a[0]), "r"(a[1]), "r"(a[2]), "r"(a[3]), "r"(b[0]), "r"(b[1]));
}
__device__ __forceinline__ uint32_t bfpack2(float a, float b) {
    __nv_bfloat16 ha = __float2bfloat16(a), hb = __float2bfloat16(b);
    uint16_t ua = *(uint16_t*)&ha, ub = *(uint16_t*)&hb;
    return (uint32_t)ua | ((uint32_t)ub << 16);
}
__device__ __forceinline__ float bfres(float v) {
    return v - __bfloat162float(__float2bfloat16(v));
}
__device__ __forceinline__ uint32_t hpack2(float a, float b) {
    __half2 h = __floats2half2_rn(a, b);
    return *(uint32_t*)&h;
}

#define QK_STRIDE 40   // b16 elems per smem row (80 B)

// ============================================================================
// Kernel 0: one-time W_qk -> fp16 (packed 8 halfs per uint4)
// ============================================================================
__global__ void wsplit_kernel(const float* __restrict__ Wqk) {
    int idx = blockIdx.x * 256 + threadIdx.x;      // 65536 items of 8 elems
    if (idx >= 1024 * 64) return;
    const float* src = &Wqk[(size_t)idx * 8];
    float v[8];
#pragma unroll
    for (int i = 0; i < 8; i++) v[i] = src[i];
    uint4 h;
    h.x = hpack2(v[0], v[1]); h.y = hpack2(v[2], v[3]);
    h.z = hpack2(v[4], v[5]); h.w = hpack2(v[6], v[7]);
    g_wh4[idx] = h;
}

// ============================================================================
// Kernel 1 (HMMA fp16, single MMA/k-step): qk[b] = W_qk @ X[b],
// bias+elu+1, fused per-CTA k column sums -> g_Sp.
// ============================================================================
__global__ __launch_bounds__(256, 2)
void qk_mma_kernel(const float* __restrict__ x,
                   const float* __restrict__ bqk) {
    __shared__ __align__(16) __half Ah[128][QK_STRIDE];
    __shared__ __align__(16) __half Bh[128][QK_STRIDE];
    __shared__ float redS[128][4];

    const int bN = blockIdx.x * 128;
    const int bM = blockIdx.y * 128;
    const int bb = blockIdx.z;
    const float* X = x + (size_t)bb * CHN * NPOS;

    const int tid = threadIdx.x;
    const int wid = tid >> 5, lane = tid & 31;
    const int wm = wid & 1;
    const int wn = wid >> 1;

    float acc[4][4][4];
#pragma unroll
    for (int i = 0; i < 4; i++)
#pragma unroll
        for (int j = 0; j < 4; j++)
#pragma unroll
            for (int r = 0; r < 4; r++) acc[i][j][r] = 0.f;

    const int nb = tid & 127;
    const int kg = tid >> 7;

    for (int c = 0; c < 16; c++) {
        const int k0 = c * 32;
        // A tile: precomputed fp16 — pure copy (2 items/thread)
#pragma unroll
        for (int r = 0; r < 2; r++) {
            int f = tid + r * 256;          // 512 items
            int row = f >> 2, qg = f & 3;   // 8-elem groups
            uint4 h = g_wh4[(bM + row) * 64 + c * 4 + qg];
            *(uint4*)&Ah[row][qg * 8] = h;
        }
        // B tile: X[k][bN+n] -> [n][k] fp16
#pragma unroll
        for (int r = 0; r < 4; r++) {
            int kk = kg * 16 + r * 4;
            const float* px = &X[(size_t)(k0 + kk) * NPOS + bN + nb];
            float v0 = px[0], v1 = px[NPOS], v2 = px[2 * NPOS], v3 = px[3 * NPOS];
            *(uint2*)&Bh[nb][kk] = make_uint2(hpack2(v0, v1), hpack2(v2, v3));
        }
        __syncthreads();

#pragma unroll
        for (int ks = 0; ks < 2; ks++) {
            uint32_t bh[4][2];
#pragma unroll
            for (int nf = 0; nf < 4; nf++) {
                int nrow = wn * 32 + nf * 8 + (lane & 7);
                int kcol = ks * 16 + ((lane >> 3) & 1) * 8;
                ldsm_x2(bh[nf], smem_u32(&Bh[nrow][kcol]));
            }
#pragma unroll
            for (int mf = 0; mf < 4; mf++) {
                int mrow = wm * 64 + mf * 16 + (lane & 15);
                int kcol = ks * 16 + (lane >> 4) * 8;
                uint32_t ah[4];
                ldsm_x4(ah, smem_u32(&Ah[mrow][kcol]));
#pragma unroll
                for (int nf = 0; nf < 4; nf++)
                    mma_f16(acc[mf][nf], ah, bh[nf]);
            }
        }
        __syncthreads();
    }

    const bool is_k = (blockIdx.y >= 4);
#pragma unroll
    for (int mf = 0; mf < 4; mf++) {
#pragma unroll
        for (int h = 0; h < 2; h++) {
            int rowg = bM + wm * 64 + mf * 16 + (lane >> 2) + h * 8;
            float bias = bqk[rowg];
            float* dst = (rowg < CHN)
                ? &g_q[((size_t)bb * CHN + rowg) * NPOS]
                : &g_k[((size_t)bb * CHN + (rowg - CHN)) * NPOS];
            float rs = 0.f;
#pragma unroll
            for (int nf = 0; nf < 4; nf++) {
                int colg = bN + wn * 32 + nf * 8 + (lane & 3) * 2;
                float2 o;
                o.x = elu1(acc[mf][nf][h * 2 + 0] + bias);
                o.y = elu1(acc[mf][nf][h * 2 + 1] + bias);
                *(float2*)&dst[colg] = o;
                rs += o.x + o.y;
            }
            if (is_k) {          // block-uniform condition; shfl safe
                rs += __shfl_xor_sync(0xffffffffu, rs, 1);
                rs += __shfl_xor_sync(0xffffffffu, rs, 2);
                if ((lane & 3) == 0)
                    redS[wm * 64 + mf * 16 + (lane >> 2) + h * 8][wn] = rs;
            }
        }
    }
    if (is_k) {
        __syncthreads();
        if (tid < 128) {
            float tot = redS[tid][0] + redS[tid][1] + redS[tid][2] + redS[tid][3];
            int kRow = bM - CHN + tid;
            g_Sp[((size_t)bb * CHN + kRow) * 72 + (bN >> 7)] = tot;
        }
    }
}

// ============================================================================
// Kernel 2: k_mean from g_Sp
// ============================================================================
__global__ void kmean_kernel() {
    int idx = blockIdx.x * 256 + threadIdx.x;
    if (idx >= BATCH * HEADS * HD) return;
    int d  = idx & 127;
    int hh = (idx >> 7) & 3;
    int bb = idx >> 9;
    float s = 0.f;
#pragma unroll
    for (int j = 0; j < 4; j++) {
        const float* p = &g_Sp[((size_t)bb * CHN + 128 * j + d) * 72 + hh * 18];
#pragma unroll
        for (int t = 0; t < 18; t++) s += p[t];
    }
    g_kmean[idx] = s * (1.f / NPOS);
}

// ============================================================================
// Kernel 3: z = 1 / (q_raw . k_mean + eps)
// ============================================================================
__global__ __launch_bounds__(256) void z_kernel() {
    const int chunk = blockIdx.x;
    const int hh = blockIdx.y, bb = blockIdx.z;
    const int tid = threadIdx.x;
    __shared__ float km[HD];
    if (tid < HD) km[tid] = g_kmean[((size_t)bb * HEADS + hh) * HD + tid];
    __syncthreads();
    const int rp = chunk * 256 + tid;
    const float* qbase = g_q + (size_t)bb * CHN * NPOS + (size_t)hh * QUARTER + rp;
    float a0 = 0.f, a1 = 0.f, a2 = 0.f, a3 = 0.f;
#pragma unroll 4
    for (int d = 0; d < HD; d++) {
        float kmv = km[d];
        a0 += qbase[(size_t)(d)       * NPOS] * kmv;
        a1 += qbase[(size_t)(128 + d) * NPOS] * kmv;
        a2 += qbase[(size_t)(256 + d) * NPOS] * kmv;
        a3 += qbase[(size_t)(384 + d) * NPOS] * kmv;
    }
    float* zb = &g_z[((size_t)bb * HEADS + hh) * NPOS + 4 * rp];
    zb[0] = 1.f / (a0 + 1e-6f);
    zb[1] = 1.f / (a1 + 1e-6f);
    zb[2] = 1.f / (a2 + 1e-6f);
    zb[3] = 1.f / (a3 + 1e-6f);
}

// ============================================================================
// Kernel 4 (HMMA bf16-split + fused RoPE): kv partials (R13-verified body)
// ============================================================================
__global__ __launch_bounds__(256, 2)
void kv_hmma_kernel(const float* __restrict__ x) {
    __shared__ __align__(16) __nv_bfloat16 Ah[128][QK_STRIDE];
    __shared__ __align__(16) __nv_bfloat16 Al[128][QK_STRIDE];
    __shared__ __align__(16) __nv_bfloat16 Bh[128][QK_STRIDE];
    __shared__ __align__(16) __nv_bfloat16 Bl[128][QK_STRIDE];

    const int chunk = blockIdx.x;
    const int hh = blockIdx.y, bb = blockIdx.z;
    const int tid = threadIdx.x;
    const int wid = tid >> 5, lane = tid & 31;
    const int wm = wid & 1, wn = wid >> 1;

    float acc[4][4][4];
#pragma unroll
    for (int i = 0; i < 4; i++)
#pragma unroll
        for (int j = 0; j < 4; j++)
#pragma unroll
            for (int r = 0; r < 4; r++) acc[i][j][r] = 0.f;

    const float* kr = &g_k[((size_t)bb * CHN + 128 * hh) * NPOS];

    float th[2], ctb[2], stb[2];
#pragma unroll
    for (int r = 0; r < 2; r++) {
        int pd = (tid + r * 256) >> 3;
        float p = (float)(64 * hh + pd);
        th[r] = expf(p * -LN1E4_256);
        sincosf(th[r], &stb[r], &ctb[r]);
    }

    for (int t = 0; t < 16; t++) {
        const int m0 = chunk * KV_CHUNK + t * 32;
#pragma unroll
        for (int r = 0; r < 2; r++) {
            int item = tid + r * 256;
            int pd = item >> 3, g = item & 7;
            const float* pre = &kr[(size_t)(2 * pd) * NPOS + m0 + 4 * g];
            float4 re4 = *(const float4*)pre;
            float4 im4 = *(const float4*)(pre + NPOS);
            float rev[4] = {re4.x, re4.y, re4.z, re4.w};
            float imv[4] = {im4.x, im4.y, im4.z, im4.w};
            int col0 = (m0 + 4 * g) % IMGW;
            float s, c;
            sincosf((float)col0 * th[r], &s, &c);
            float ore[4], oim[4];
#pragma unroll
            for (int i = 0; i < 4; i++) {
                ore[i] = c * rev[i] - s * imv[i];
                oim[i] = s * rev[i] + c * imv[i];
                float cn = c * ctb[r] - s * stb[r];
                s = s * ctb[r] + c * stb[r];
                c = cn;
            }
            *(uint2*)&Ah[2 * pd][4 * g]     = make_uint2(bfpack2(ore[0], ore[1]), bfpack2(ore[2], ore[3]));
            *(uint2*)&Ah[2 * pd + 1][4 * g] = make_uint2(bfpack2(oim[0], oim[1]), bfpack2(oim[2], oim[3]));
            *(uint2*)&Al[2 * pd][4 * g]     = make_uint2(bfpack2(bfres(ore[0]), bfres(ore[1])),
                                                          bfpack2(bfres(ore[2]), bfres(ore[3])));
            *(uint2*)&Al[2 * pd + 1][4 * g] = make_uint2(bfpack2(bfres(oim[0]), bfres(oim[1])),
                                                          bfpack2(bfres(oim[2]), bfres(oim[3])));
        }
        {
            const int posb = hh * QUARTER + (m0 >> 2);
            int rg = tid & 1, j = (tid >> 1) & 3, ebase = tid >> 3;
#pragma unroll
            for (int r = 0; r < 4; r++) {
                int e = ebase + 32 * r;
                float4 v = *(const float4*)(x + ((size_t)bb * CHN + 128 * j + e) * NPOS + posb + rg * 4);
                float vv[4] = {v.x, v.y, v.z, v.w};
#pragma unroll
                for (int u = 0; u < 4; u++) {
                    int ml = 4 * (rg * 4 + u) + j;
                    __nv_bfloat16 h = __float2bfloat16(vv[u]);
                    Bh[e][ml] = h;
                    Bl[e][ml] = __float2bfloat16(vv[u] - __bfloat162float(h));
                }
            }
        }
        __syncthreads();

#pragma unroll
        for (int ks = 0; ks < 2; ks++) {
            uint32_t bh[4][2], bl[4][2];
#pragma unroll
            for (int nf = 0; nf < 4; nf++) {
                int nrow = wn * 32 + nf * 8 + (lane & 7);
                int kcol = ks * 16 + ((lane >> 3) & 1) * 8;
                ldsm_x2(bh[nf], smem_u32(&Bh[nrow][kcol]));
                ldsm_x2(bl[nf], smem_u32(&Bl[nrow][kcol]));
            }
#pragma unroll
            for (int mf = 0; mf < 4; mf++) {
                int mrow = wm * 64 + mf * 16 + (lane & 15);
                int kcol = ks * 16 + (lane >> 4) * 8;
                uint32_t ah[4], al[4];
                ldsm_x4(ah, smem_u32(&Ah[mrow][kcol]));
                ldsm_x4(al, smem_u32(&Al[mrow][kcol]));
#pragma unroll
                for (int nf = 0; nf < 4; nf++) {
                    mma_bf16(acc[mf][nf], ah, bh[nf]);
                    mma_bf16(acc[mf][nf], ah, bl[nf]);
                    mma_bf16(acc[mf][nf], al, bh[nf]);
                }
            }
        }
        __syncthreads();
    }

    float* dst = &g_kvp[(((size_t)(bb * HEADS + hh)) * KV_SPLIT + chunk) * HD * HD];
#pragma unroll
    for (int mf = 0; mf < 4; mf++) {
#pragma unroll
        for (int h = 0; h < 2; h++) {
            int d = wm * 64 + mf * 16 + (lane >> 2) + h * 8;
#pragma unroll
            for (int nf = 0; nf < 4; nf++) {
                int e = wn * 32 + nf * 8 + (lane & 3) * 2;
                *(float2*)&dst[d * HD + e] =
                    make_float2(acc[mf][nf][h * 2 + 0], acc[mf][nf][h * 2 + 1]);
            }
        }
    }
}

__global__ void kvreduce_kernel() {
    int idx = blockIdx.x * 256 + threadIdx.x;
    int bh  = idx >> 14;
    int off = idx & 16383;
    const float* p = &g_kvp[((size_t)bh * KV_SPLIT) * HD * HD + off];
    float s = 0.f;
#pragma unroll
    for (int c = 0; c < KV_SPLIT; c++) s += p[(size_t)c * HD * HD];
    g_kv[idx] = s * (1.f / NPOS);
}

// ============================================================================
// Kernel 6 (HMMA bf16-split + fused RoPE): out (R13-verified body)
// ============================================================================
__global__ __launch_bounds__(256, 2)
void out_hmma_kernel(float* __restrict__ out) {
    __shared__ __align__(16) __nv_bfloat16 Ah[128][QK_STRIDE];
    __shared__ __align__(16) __nv_bfloat16 Al[128][QK_STRIDE];
    __shared__ __align__(16) __nv_bfloat16 Bh[128][QK_STRIDE];
    __shared__ __align__(16) __nv_bfloat16 Bl[128][QK_STRIDE];

    const int m0 = blockIdx.x * 128;
    const int hh = blockIdx.y, bb = blockIdx.z;
    const int tid = threadIdx.x;
    const int wid = tid >> 5, lane = tid & 31;
    const int wm = wid & 1, wn = wid >> 1;

    float acc[4][4][4];
#pragma unroll
    for (int i = 0; i < 4; i++)
#pragma unroll
        for (int j = 0; j < 4; j++)
#pragma unroll
            for (int r = 0; r < 4; r++) acc[i][j][r] = 0.f;

    const float* qr  = &g_q[((size_t)bb * CHN + 128 * hh) * NPOS];
    const float* kvm = &g_kv[((size_t)(bb * HEADS) + hh) * HD * HD];

    for (int dc = 0; dc < 4; dc++) {
        const int d0 = dc * 32;
#pragma unroll
        for (int r = 0; r < 4; r++) {
            int item = tid + r * 256;
            int dk = item >> 5, eg = item & 31;
            float4 v = *(const float4*)&kvm[(d0 + dk) * HD + 4 * eg];
            float vv[4] = {v.x, v.y, v.z, v.w};
#pragma unroll
            for (int i = 0; i < 4; i++) {
                int e = 4 * eg + i;
                __nv_bfloat16 h = __float2bfloat16(vv[i]);
                Ah[e][dk] = h;
                Al[e][dk] = __float2bfloat16(vv[i] - __bfloat162float(h));
            }
        }
#pragma unroll
        for (int r = 0; r < 2; r++) {
            int item = tid + r * 256;
            int u = item >> 5, g = item & 31;
            const float* pre = &qr[(size_t)(d0 + 2 * u) * NPOS + m0 + 4 * g];
            float4 re4 = *(const float4*)pre;
            float4 im4 = *(const float4*)(pre + NPOS);
            float rev[4] = {re4.x, re4.y, re4.z, re4.w};
            float imv[4] = {im4.x, im4.y, im4.z, im4.w};
            float p = (float)(64 * hh + (d0 >> 1) + u);
            float theta = expf(p * -LN1E4_256);
            float ct, st;
            sincosf(theta, &st, &ct);
            int col0 = (m0 + 4 * g) % IMGW;
            float s, c;
            sincosf((float)col0 * theta, &s, &c);
#pragma unroll
            for (int i = 0; i < 4; i++) {
                float ore = c * rev[i] - s * imv[i];
                float oim = s * rev[i] + c * imv[i];
                int m = 4 * g + i;
                __nv_bfloat16 hr = __float2bfloat16(ore);
                __nv_bfloat16 hi = __float2bfloat16(oim);
                Bh[m][2 * u]     = hr;
                Bh[m][2 * u + 1] = hi;
                Bl[m][2 * u]     = __float2bfloat16(ore - __bfloat162float(hr));
                Bl[m][2 * u + 1] = __float2bfloat16(oim - __bfloat162float(hi));
                float cn = c * ct - s * st;
                s = s * ct + c * st;
                c = cn;
            }
        }
        __syncthreads();

#pragma unroll
        for (int ks = 0; ks < 2; ks++) {
            uint32_t bh[4][2], bl[4][2];
#pragma unroll
            for (int nf = 0; nf < 4; nf++) {
                int nrow = wn * 32 + nf * 8 + (lane & 7);
                int kcol = ks * 16 + ((lane >> 3) & 1) * 8;
                ldsm_x2(bh[nf], smem_u32(&Bh[nrow][kcol]));
                ldsm_x2(bl[nf], smem_u32(&Bl[nrow][kcol]));
            }
#pragma unroll
            for (int mf = 0; mf < 4; mf++) {
                int mrow = wm * 64 + mf * 16 + (lane & 15);
                int kcol = ks * 16 + (lane >> 4) * 8;
                uint32_t ah[4], al[4];
                ldsm_x4(ah, smem_u32(&Ah[mrow][kcol]));
                ldsm_x4(al, smem_u32(&Al[mrow][kcol]));
#pragma unroll
                for (int nf = 0; nf < 4; nf++) {
                    mma_bf16(acc[mf][nf], ah, bh[nf]);
                    mma_bf16(acc[mf][nf], ah, bl[nf]);
                    mma_bf16(acc[mf][nf], al, bh[nf]);
                }
            }
        }
        __syncthreads();
    }

    const float* zb = &g_z[((size_t)bb * HEADS + hh) * NPOS + m0];
#pragma unroll
    for (int mf = 0; mf < 4; mf++) {
#pragma unroll
        for (int h = 0; h < 2; h++) {
            int e = wm * 64 + mf * 16 + (lane >> 2) + h * 8;
            float* dst = out + ((size_t)bb * CHN + 128 * hh + e) * NPOS + m0;
#pragma unroll
            for (int nf = 0; nf < 4; nf++) {
                int ml = wn * 32 + nf * 8 + (lane & 3) * 2;
                float2 o;
                o.x = acc[mf][nf][h * 2 + 0] * zb[ml + 0];
                o.y = acc[mf][nf][h * 2 + 1] * zb[ml + 1];
                *(float2*)&dst[ml] = o;
            }
        }
    }
}

// ============================================================================
// Kernel 7: lepe — depthwise 3x3 conv, out += conv + bias
// ============================================================================
__global__ __launch_bounds__(256) void lepe_kernel(const float* __restrict__ x,
                                                   const float* __restrict__ w,
                                                   const float* __restrict__ bias,
                                                   float* __restrict__ out) {
    const int c = blockIdx.x, bb = blockIdx.y;
    __shared__ float plane[NPOS];
    const float* src = x + ((size_t)bb * CHN + c) * NPOS;
    const int tid = threadIdx.x;
    for (int i = tid; i < NPOS; i += 256) plane[i] = src[i];
    float wv[9];
#pragma unroll
    for (int kk = 0; kk < 9; kk++) wv[kk] = w[c * 9 + kk];
    const float bv = bias[c];
    __syncthreads();

    float* dst = out + ((size_t)bb * CHN + c) * NPOS;
    for (int i = tid; i < NPOS; i += 256) {
        int y = i / IMGW;
        int xx = i - y * IMGW;
        float s = bv;
#pragma unroll
        for (int ky = 0; ky < 3; ky++) {
            int yy = y + ky - 1;
            if (yy < 0 || yy >= IMGW) continue;
#pragma unroll
            for (int kx = 0; kx < 3; kx++) {
                int xs = xx + kx - 1;
                if (xs < 0 || xs >= IMGW) continue;
                s += wv[ky * 3 + kx] * plane[yy * IMGW + xs];
            }
        }
        dst[i] += s;
    }
}

// ============================================================================
extern "C" void kernel_launch(void* const* d_in, const int* in_sizes, int n_in,
                              void* d_out, int out_size) {
    (void)in_sizes; (void)n_in; (void)out_size;
    const float* x    = (const float*)d_in[0];
    const float* Wqk  = (const float*)d_in[1];
    const float* bqk  = (const float*)d_in[2];
    const float* lw   = (const float*)d_in[3];
    const float* lb   = (const float*)d_in[4];
    float* out = (float*)d_out;

    // 0) one-time W -> fp16
    wsplit_kernel<<<256, 256>>>(Wqk);
    // 1) q,k = elu(W_qk @ x + b) + 1  + fused k column sums (fp16 single MMA)
    qk_mma_kernel<<<dim3(72, 8, BATCH), 256>>>(x, bqk);
    // 2) k_mean from g_Sp
    kmean_kernel<<<16, 256>>>();
    // 3) z (raw q)
    z_kernel<<<dim3(9, HEADS, BATCH), 256>>>();
    // 4) kv = rope(k) @ v  (split-K + reduce, bf16 3-MMA)
    kv_hmma_kernel<<<dim3(KV_SPLIT, HEADS, BATCH), 256>>>(x);
    kvreduce_kernel<<<2048, 256>>>();
    // 5) out = z * (rope(q) @ kv)  (bf16 3-MMA)
    out_hmma_kernel<<<dim3(72, HEADS, BATCH), 256>>>(out);
    // 6) out += depthwise3x3(x) + bias
    lepe_kernel<<<dim3(CHN, BATCH), 256>>>(x, lw, lb, out);
}